// round 11
// baseline (speedup 1.0000x reference)
#include <cuda_runtime.h>
#include <cstdint>
#include <math.h>

// ---------------------------------------------------------------------------
// Switcher: per-batch-column 2-expert MLP, tf32 mma.sync, fp32 accum.
//   e(b) = lang_ids[b] >= 12
//   out[s,b,:] = W2_e @ gelu(W1_e @ x[s,b,:] + b1_e) + b2_e  (exact erf gelu)
//
// R5: cp.async double-buffered pipeline.
//  - prepass converts W1/W2 to tf32 (rna) into __device__ scratch
//  - unified 64-chunk ring: chunks 0..31 = stage1 (X tile + W1 tile),
//    chunks 32..63 = stage2 W2 tiles (4 N-groups x 8 K-chunks)
//  - one __syncthreads per chunk; cp.async for k+1 overlaps compute of k
//  - XOR-swizzled smem (conflict-free), biases via __ldg
// ---------------------------------------------------------------------------

namespace {

constexpr int SEQ    = 2048;
constexpr int BZ     = 64;
constexpr int DIM    = 1024;
constexpr int HID    = 256;
constexpr int TILE_S = 128;
constexpr int KC     = 32;

// smem word offsets
constexpr int SH_OFF = 0;                     // sH: [128][256] swizzled
constexpr int XB_OFF = 32768;                 // xbuf: 2 x [128][32] swizzled
constexpr int WB_OFF = XB_OFF + 2 * 4096;     // wbuf: 2 x [256][32] swizzled
constexpr int SMEM_WORDS = WB_OFF + 2 * 8192; // 57344 words
constexpr int SMEM_BYTES = SMEM_WORDS * 4;    // 229376 B (224 KB)

// pre-converted tf32 weights (values tf32-rounded, stored as u32)
__device__ uint32_t g_w1[2 * HID * DIM];
__device__ uint32_t g_w2[2 * DIM * HID];

__device__ __forceinline__ uint32_t f2tf(float x) {
    uint32_t u;
    asm("cvt.rna.tf32.f32 %0, %1;" : "=r"(u) : "f"(x));
    return u;
}

__device__ __forceinline__ void mma8(float d[4], const uint32_t a[4], const uint32_t b[2]) {
    asm volatile(
        "mma.sync.aligned.m16n8k8.row.col.f32.tf32.tf32.f32 "
        "{%0,%1,%2,%3}, {%4,%5,%6,%7}, {%8,%9}, {%0,%1,%2,%3};\n"
        : "+f"(d[0]), "+f"(d[1]), "+f"(d[2]), "+f"(d[3])
        : "r"(a[0]), "r"(a[1]), "r"(a[2]), "r"(a[3]),
          "r"(b[0]), "r"(b[1]));
}

__device__ __forceinline__ void cp16(uint32_t dst_smem, const void* src) {
    asm volatile("cp.async.cg.shared.global [%0], [%1], 16;\n"
                 :: "r"(dst_smem), "l"(src));
}

__device__ __forceinline__ float gelu_exact(float v) {
    return 0.5f * v * (1.0f + erff(v * 0.70710678118654752440f));
}

// ------------------------- prepass: fp32 -> tf32 ---------------------------
__global__ void __launch_bounds__(256)
convert_weights(const float* __restrict__ w1, const float* __restrict__ w2) {
    int i = (blockIdx.x * 256 + threadIdx.x) * 4;
    if (i < 2 * HID * DIM) {
        float4 a = *(const float4*)(w1 + i);
        *(uint4*)(g_w1 + i) = make_uint4(f2tf(a.x), f2tf(a.y), f2tf(a.z), f2tf(a.w));
        float4 c = *(const float4*)(w2 + i);
        *(uint4*)(g_w2 + i) = make_uint4(f2tf(c.x), f2tf(c.y), f2tf(c.z), f2tf(c.w));
    }
}

// ------------------------------ main kernel --------------------------------
__global__ void __launch_bounds__(256, 1)
switcher_kernel(const float* __restrict__ x,
                const int*   __restrict__ lang_ids,
                const float* __restrict__ w1_b,
                const float* __restrict__ w2_b,
                float*       __restrict__ out)
{
    extern __shared__ uint32_t smem[];
    uint32_t* sH = smem + SH_OFF;
    const uint32_t smem_u = (uint32_t)__cvta_generic_to_shared(smem);

    const int tid  = threadIdx.x;
    const int lane = tid & 31;
    const int warp = tid >> 5;
    const int lr   = lane >> 2;         // 0..7
    const int lc   = lane & 3;          // 0..3
    const int swz  = lr << 2;           // smem XOR swizzle for this thread's rows
    const int wm   = (warp >> 2) * 64;  // {0,64}
    const int wn   = (warp & 3) * 64;   // {0,64,128,192}

    const int s0 = blockIdx.x * TILE_S;
    const int b  = blockIdx.y;
    const int e  = (lang_ids[b] >= 12) ? 1 : 0;

    const uint32_t* w1 = g_w1 + (size_t)e * HID * DIM;
    const uint32_t* w2 = g_w2 + (size_t)e * DIM * HID;

    // issue cp.async for chunk c into buffer (c&1), then commit a group.
    auto issue = [&](int c) {
        const uint32_t dstX = smem_u + (XB_OFF + (c & 1) * 4096) * 4;
        const uint32_t dstW = smem_u + (WB_OFF + (c & 1) * 8192) * 4;
        if (c < 32) {
            const int kc = c * KC;
            #pragma unroll
            for (int it = 0; it < 4; ++it) {           // X tile: 128x32
                int unit = tid + it * 256;
                int r = unit >> 3, c4 = (unit & 7) << 2;
                cp16(dstX + (r * 32 + (c4 ^ ((r & 7) << 2))) * 4,
                     x + ((size_t)(s0 + r) * BZ + b) * DIM + kc + c4);
            }
            #pragma unroll
            for (int it = 0; it < 8; ++it) {           // W1 tile: 256x32
                int unit = tid + it * 256;
                int r = unit >> 3, c4 = (unit & 7) << 2;
                cp16(dstW + (r * 32 + (c4 ^ ((r & 7) << 2))) * 4,
                     w1 + (size_t)r * DIM + kc + c4);
            }
        } else {
            const int cc = c - 32;
            const int n2 = cc >> 3;
            const int kc = (cc & 7) * KC;
            const uint32_t* wsrc = w2 + (size_t)n2 * 256 * HID;
            #pragma unroll
            for (int it = 0; it < 8; ++it) {           // W2 tile: 256x32
                int unit = tid + it * 256;
                int r = unit >> 3, c4 = (unit & 7) << 2;
                cp16(dstW + (r * 32 + (c4 ^ ((r & 7) << 2))) * 4,
                     wsrc + (size_t)r * HID + kc + c4);
            }
        }
        asm volatile("cp.async.commit_group;\n");
    };

    float acc[4][8][4];
    #pragma unroll
    for (int im = 0; im < 4; ++im)
        #pragma unroll
        for (int in = 0; in < 8; ++in)
            #pragma unroll
            for (int q = 0; q < 4; ++q) acc[im][in][q] = 0.0f;

    issue(0);

    // ================= stage 1: H = gelu(X @ W1^T + b1) =================
    #pragma unroll 1
    for (int c = 0; c < 32; ++c) {
        const int p = c & 1;
        asm volatile("cp.async.wait_group 0;\n" ::: "memory");
        __syncthreads();
        issue(c + 1);

        const uint32_t* xt = smem + XB_OFF + p * 4096;
        const uint32_t* wt = smem + WB_OFF + p * 8192;

        #pragma unroll
        for (int ks = 0; ks < 4; ++ks) {
            const int kk   = ks * 8;
            const int col0 = (kk + lc) ^ swz;
            const int col1 = (kk + lc + 4) ^ swz;
            uint32_t afr[4][4], bfr[8][2];
            #pragma unroll
            for (int im = 0; im < 4; ++im) {
                int r = wm + im * 16 + lr;
                afr[im][0] = f2tf(__uint_as_float(xt[r * 32 + col0]));
                afr[im][1] = f2tf(__uint_as_float(xt[(r + 8) * 32 + col0]));
                afr[im][2] = f2tf(__uint_as_float(xt[r * 32 + col1]));
                afr[im][3] = f2tf(__uint_as_float(xt[(r + 8) * 32 + col1]));
            }
            #pragma unroll
            for (int in = 0; in < 8; ++in) {
                int n = wn + in * 8 + lr;
                bfr[in][0] = wt[n * 32 + col0];
                bfr[in][1] = wt[n * 32 + col1];
            }
            #pragma unroll
            for (int im = 0; im < 4; ++im)
                #pragma unroll
                for (int in = 0; in < 8; ++in)
                    mma8(acc[im][in], afr[im], bfr[in]);
        }
    }

    // epilogue: bias + exact gelu -> sH (tf32, swizzled). The first stage-2
    // chunk's __syncthreads orders these writes before any sH read.
    #pragma unroll
    for (int im = 0; im < 4; ++im) {
        #pragma unroll
        for (int in = 0; in < 8; ++in) {
            int r = wm + im * 16 + lr;
            int cN = wn + in * 8 + lc * 2;
            float bb0 = __ldg(w1_b + e * HID + cN);
            float bb1 = __ldg(w1_b + e * HID + cN + 1);
            int pc = cN ^ swz;
            uint32_t h00 = f2tf(gelu_exact(acc[im][in][0] + bb0));
            uint32_t h01 = f2tf(gelu_exact(acc[im][in][1] + bb1));
            uint32_t h10 = f2tf(gelu_exact(acc[im][in][2] + bb0));
            uint32_t h11 = f2tf(gelu_exact(acc[im][in][3] + bb1));
            *(uint2*)(sH + r * 256 + pc)       = make_uint2(h00, h01);
            *(uint2*)(sH + (r + 8) * 256 + pc) = make_uint2(h10, h11);
        }
    }

    // ============ stage 2: OUT = H @ W2^T + b2, 4 N-groups of 256 ============
    #pragma unroll 1
    for (int n2 = 0; n2 < 4; ++n2) {
        #pragma unroll
        for (int im = 0; im < 4; ++im)
            #pragma unroll
            for (int in = 0; in < 8; ++in)
                #pragma unroll
                for (int q = 0; q < 4; ++q) acc[im][in][q] = 0.0f;

        #pragma unroll 1
        for (int kci = 0; kci < 8; ++kci) {
            const int c = 32 + n2 * 8 + kci;
            const int p = c & 1;
            asm volatile("cp.async.wait_group 0;\n" ::: "memory");
            __syncthreads();
            if (c + 1 < 64) issue(c + 1);

            const uint32_t* wt = smem + WB_OFF + p * 8192;

            #pragma unroll
            for (int ks = 0; ks < 4; ++ks) {
                const int kkH = kci * KC + ks * 8;
                const int kkW = ks * 8;
                const int ch0 = (kkH + lc) ^ swz;
                const int ch1 = (kkH + lc + 4) ^ swz;
                const int cw0 = (kkW + lc) ^ swz;
                const int cw1 = (kkW + lc + 4) ^ swz;
                uint32_t afr[4][4], bfr[8][2];
                #pragma unroll
                for (int im = 0; im < 4; ++im) {
                    int r = wm + im * 16 + lr;
                    afr[im][0] = sH[r * 256 + ch0];
                    afr[im][1] = sH[(r + 8) * 256 + ch0];
                    afr[im][2] = sH[r * 256 + ch1];
                    afr[im][3] = sH[(r + 8) * 256 + ch1];
                }
                #pragma unroll
                for (int in = 0; in < 8; ++in) {
                    int n = wn + in * 8 + lr;
                    bfr[in][0] = wt[n * 32 + cw0];
                    bfr[in][1] = wt[n * 32 + cw1];
                }
                #pragma unroll
                for (int im = 0; im < 4; ++im)
                    #pragma unroll
                    for (int in = 0; in < 8; ++in)
                        mma8(acc[im][in], afr[im], bfr[in]);
            }
        }

        // epilogue: bias + store fp32
        #pragma unroll
        for (int im = 0; im < 4; ++im) {
            #pragma unroll
            for (int in = 0; in < 8; ++in) {
                int r  = wm + im * 16 + lr;
                int cN = wn + in * 8 + lc * 2;
                int gc = n2 * 256 + cN;
                float bb0 = __ldg(w2_b + e * DIM + gc);
                float bb1 = __ldg(w2_b + e * DIM + gc + 1);
                float2 v0 = make_float2(acc[im][in][0] + bb0, acc[im][in][1] + bb1);
                float2 v1 = make_float2(acc[im][in][2] + bb0, acc[im][in][3] + bb1);
                *(float2*)(out + ((size_t)(s0 + r) * BZ + b) * DIM + gc)     = v0;
                *(float2*)(out + ((size_t)(s0 + r + 8) * BZ + b) * DIM + gc) = v1;
            }
        }
    }
}

}  // namespace

extern "C" void kernel_launch(void* const* d_in, const int* in_sizes, int n_in,
                              void* d_out, int out_size) {
    const float* x        = (const float*)d_in[0];
    const int*   lang_ids = (const int*)  d_in[1];
    const float* w1_w     = (const float*)d_in[2];
    const float* w1_b     = (const float*)d_in[3];
    const float* w2_w     = (const float*)d_in[4];
    const float* w2_b     = (const float*)d_in[5];
    float*       out      = (float*)d_out;

    cudaFuncSetAttribute(switcher_kernel,
                         cudaFuncAttributeMaxDynamicSharedMemorySize, SMEM_BYTES);

    // prepass: fp32 -> tf32 weights (4 MB, ~2us)
    convert_weights<<<512, 256>>>(w1_w, w2_w);

    dim3 grid(SEQ / TILE_S, BZ);
    switcher_kernel<<<grid, 256, SMEM_BYTES>>>(x, lang_ids, w1_b, w2_b, out);
}

// round 12
// speedup vs baseline: 1.0005x; 1.0005x over previous
#include <cuda_runtime.h>
#include <cstdint>
#include <math.h>

// ---------------------------------------------------------------------------
// Switcher: per-batch-column 2-expert MLP, tf32 mma.sync, fp32 accum.
//   e(b) = lang_ids[b] >= 12
//   out[s,b,:] = W2_e @ gelu(W1_e @ x[s,b,:] + b1_e) + b2_e  (exact erf gelu)
//
// R5: cp.async double-buffered pipeline.
//  - prepass converts W1/W2 to tf32 (rna) into __device__ scratch
//  - unified 64-chunk ring: chunks 0..31 = stage1 (X tile + W1 tile),
//    chunks 32..63 = stage2 W2 tiles (4 N-groups x 8 K-chunks)
//  - one __syncthreads per chunk; cp.async for k+1 overlaps compute of k
//  - XOR-swizzled smem (conflict-free), biases via __ldg
// ---------------------------------------------------------------------------

namespace {

constexpr int SEQ    = 2048;
constexpr int BZ     = 64;
constexpr int DIM    = 1024;
constexpr int HID    = 256;
constexpr int TILE_S = 128;
constexpr int KC     = 32;

// smem word offsets
constexpr int SH_OFF = 0;                     // sH: [128][256] swizzled
constexpr int XB_OFF = 32768;                 // xbuf: 2 x [128][32] swizzled
constexpr int WB_OFF = XB_OFF + 2 * 4096;     // wbuf: 2 x [256][32] swizzled
constexpr int SMEM_WORDS = WB_OFF + 2 * 8192; // 57344 words
constexpr int SMEM_BYTES = SMEM_WORDS * 4;    // 229376 B (224 KB)

// pre-converted tf32 weights (values tf32-rounded, stored as u32)
__device__ uint32_t g_w1[2 * HID * DIM];
__device__ uint32_t g_w2[2 * DIM * HID];

__device__ __forceinline__ uint32_t f2tf(float x) {
    uint32_t u;
    asm("cvt.rna.tf32.f32 %0, %1;" : "=r"(u) : "f"(x));
    return u;
}

__device__ __forceinline__ void mma8(float d[4], const uint32_t a[4], const uint32_t b[2]) {
    asm volatile(
        "mma.sync.aligned.m16n8k8.row.col.f32.tf32.tf32.f32 "
        "{%0,%1,%2,%3}, {%4,%5,%6,%7}, {%8,%9}, {%0,%1,%2,%3};\n"
        : "+f"(d[0]), "+f"(d[1]), "+f"(d[2]), "+f"(d[3])
        : "r"(a[0]), "r"(a[1]), "r"(a[2]), "r"(a[3]),
          "r"(b[0]), "r"(b[1]));
}

__device__ __forceinline__ void cp16(uint32_t dst_smem, const void* src) {
    asm volatile("cp.async.cg.shared.global [%0], [%1], 16;\n"
                 :: "r"(dst_smem), "l"(src));
}

__device__ __forceinline__ float gelu_exact(float v) {
    return 0.5f * v * (1.0f + erff(v * 0.70710678118654752440f));
}

// ------------------------- prepass: fp32 -> tf32 ---------------------------
__global__ void __launch_bounds__(256)
convert_weights(const float* __restrict__ w1, const float* __restrict__ w2) {
    int i = (blockIdx.x * 256 + threadIdx.x) * 4;
    if (i < 2 * HID * DIM) {
        float4 a = *(const float4*)(w1 + i);
        *(uint4*)(g_w1 + i) = make_uint4(f2tf(a.x), f2tf(a.y), f2tf(a.z), f2tf(a.w));
        float4 c = *(const float4*)(w2 + i);
        *(uint4*)(g_w2 + i) = make_uint4(f2tf(c.x), f2tf(c.y), f2tf(c.z), f2tf(c.w));
    }
}

// ------------------------------ main kernel --------------------------------
__global__ void __launch_bounds__(256, 1)
switcher_kernel(const float* __restrict__ x,
                const int*   __restrict__ lang_ids,
                const float* __restrict__ w1_b,
                const float* __restrict__ w2_b,
                float*       __restrict__ out)
{
    extern __shared__ uint32_t smem[];
    uint32_t* sH = smem + SH_OFF;
    const uint32_t smem_u = (uint32_t)__cvta_generic_to_shared(smem);

    const int tid  = threadIdx.x;
    const int lane = tid & 31;
    const int warp = tid >> 5;
    const int lr   = lane >> 2;         // 0..7
    const int lc   = lane & 3;          // 0..3
    const int swz  = lr << 2;           // smem XOR swizzle for this thread's rows
    const int wm   = (warp >> 2) * 64;  // {0,64}
    const int wn   = (warp & 3) * 64;   // {0,64,128,192}

    const int s0 = blockIdx.x * TILE_S;
    const int b  = blockIdx.y;
    const int e  = (lang_ids[b] >= 12) ? 1 : 0;

    const uint32_t* w1 = g_w1 + (size_t)e * HID * DIM;
    const uint32_t* w2 = g_w2 + (size_t)e * DIM * HID;

    // issue cp.async for chunk c into buffer (c&1), then commit a group.
    auto issue = [&](int c) {
        const uint32_t dstX = smem_u + (XB_OFF + (c & 1) * 4096) * 4;
        const uint32_t dstW = smem_u + (WB_OFF + (c & 1) * 8192) * 4;
        if (c < 32) {
            const int kc = c * KC;
            #pragma unroll
            for (int it = 0; it < 4; ++it) {           // X tile: 128x32
                int unit = tid + it * 256;
                int r = unit >> 3, c4 = (unit & 7) << 2;
                cp16(dstX + (r * 32 + (c4 ^ ((r & 7) << 2))) * 4,
                     x + ((size_t)(s0 + r) * BZ + b) * DIM + kc + c4);
            }
            #pragma unroll
            for (int it = 0; it < 8; ++it) {           // W1 tile: 256x32
                int unit = tid + it * 256;
                int r = unit >> 3, c4 = (unit & 7) << 2;
                cp16(dstW + (r * 32 + (c4 ^ ((r & 7) << 2))) * 4,
                     w1 + (size_t)r * DIM + kc + c4);
            }
        } else {
            const int cc = c - 32;
            const int n2 = cc >> 3;
            const int kc = (cc & 7) * KC;
            const uint32_t* wsrc = w2 + (size_t)n2 * 256 * HID;
            #pragma unroll
            for (int it = 0; it < 8; ++it) {           // W2 tile: 256x32
                int unit = tid + it * 256;
                int r = unit >> 3, c4 = (unit & 7) << 2;
                cp16(dstW + (r * 32 + (c4 ^ ((r & 7) << 2))) * 4,
                     wsrc + (size_t)r * HID + kc + c4);
            }
        }
        asm volatile("cp.async.commit_group;\n");
    };

    float acc[4][8][4];
    #pragma unroll
    for (int im = 0; im < 4; ++im)
        #pragma unroll
        for (int in = 0; in < 8; ++in)
            #pragma unroll
            for (int q = 0; q < 4; ++q) acc[im][in][q] = 0.0f;

    issue(0);

    // ================= stage 1: H = gelu(X @ W1^T + b1) =================
    #pragma unroll 1
    for (int c = 0; c < 32; ++c) {
        const int p = c & 1;
        asm volatile("cp.async.wait_group 0;\n" ::: "memory");
        __syncthreads();
        issue(c + 1);

        const uint32_t* xt = smem + XB_OFF + p * 4096;
        const uint32_t* wt = smem + WB_OFF + p * 8192;

        #pragma unroll
        for (int ks = 0; ks < 4; ++ks) {
            const int kk   = ks * 8;
            const int col0 = (kk + lc) ^ swz;
            const int col1 = (kk + lc + 4) ^ swz;
            uint32_t afr[4][4], bfr[8][2];
            #pragma unroll
            for (int im = 0; im < 4; ++im) {
                int r = wm + im * 16 + lr;
                afr[im][0] = f2tf(__uint_as_float(xt[r * 32 + col0]));
                afr[im][1] = f2tf(__uint_as_float(xt[(r + 8) * 32 + col0]));
                afr[im][2] = f2tf(__uint_as_float(xt[r * 32 + col1]));
                afr[im][3] = f2tf(__uint_as_float(xt[(r + 8) * 32 + col1]));
            }
            #pragma unroll
            for (int in = 0; in < 8; ++in) {
                int n = wn + in * 8 + lr;
                bfr[in][0] = wt[n * 32 + col0];
                bfr[in][1] = wt[n * 32 + col1];
            }
            #pragma unroll
            for (int im = 0; im < 4; ++im)
                #pragma unroll
                for (int in = 0; in < 8; ++in)
                    mma8(acc[im][in], afr[im], bfr[in]);
        }
    }

    // epilogue: bias + exact gelu -> sH (tf32, swizzled). The first stage-2
    // chunk's __syncthreads orders these writes before any sH read.
    #pragma unroll
    for (int im = 0; im < 4; ++im) {
        #pragma unroll
        for (int in = 0; in < 8; ++in) {
            int r = wm + im * 16 + lr;
            int cN = wn + in * 8 + lc * 2;
            float bb0 = __ldg(w1_b + e * HID + cN);
            float bb1 = __ldg(w1_b + e * HID + cN + 1);
            int pc = cN ^ swz;
            uint32_t h00 = f2tf(gelu_exact(acc[im][in][0] + bb0));
            uint32_t h01 = f2tf(gelu_exact(acc[im][in][1] + bb1));
            uint32_t h10 = f2tf(gelu_exact(acc[im][in][2] + bb0));
            uint32_t h11 = f2tf(gelu_exact(acc[im][in][3] + bb1));
            *(uint2*)(sH + r * 256 + pc)       = make_uint2(h00, h01);
            *(uint2*)(sH + (r + 8) * 256 + pc) = make_uint2(h10, h11);
        }
    }

    // ============ stage 2: OUT = H @ W2^T + b2, 4 N-groups of 256 ============
    #pragma unroll 1
    for (int n2 = 0; n2 < 4; ++n2) {
        #pragma unroll
        for (int im = 0; im < 4; ++im)
            #pragma unroll
            for (int in = 0; in < 8; ++in)
                #pragma unroll
                for (int q = 0; q < 4; ++q) acc[im][in][q] = 0.0f;

        #pragma unroll 1
        for (int kci = 0; kci < 8; ++kci) {
            const int c = 32 + n2 * 8 + kci;
            const int p = c & 1;
            asm volatile("cp.async.wait_group 0;\n" ::: "memory");
            __syncthreads();
            if (c + 1 < 64) issue(c + 1);

            const uint32_t* wt = smem + WB_OFF + p * 8192;

            #pragma unroll
            for (int ks = 0; ks < 4; ++ks) {
                const int kkH = kci * KC + ks * 8;
                const int kkW = ks * 8;
                const int ch0 = (kkH + lc) ^ swz;
                const int ch1 = (kkH + lc + 4) ^ swz;
                const int cw0 = (kkW + lc) ^ swz;
                const int cw1 = (kkW + lc + 4) ^ swz;
                uint32_t afr[4][4], bfr[8][2];
                #pragma unroll
                for (int im = 0; im < 4; ++im) {
                    int r = wm + im * 16 + lr;
                    afr[im][0] = sH[r * 256 + ch0];
                    afr[im][1] = sH[(r + 8) * 256 + ch0];
                    afr[im][2] = sH[r * 256 + ch1];
                    afr[im][3] = sH[(r + 8) * 256 + ch1];
                }
                #pragma unroll
                for (int in = 0; in < 8; ++in) {
                    int n = wn + in * 8 + lr;
                    bfr[in][0] = wt[n * 32 + cw0];
                    bfr[in][1] = wt[n * 32 + cw1];
                }
                #pragma unroll
                for (int im = 0; im < 4; ++im)
                    #pragma unroll
                    for (int in = 0; in < 8; ++in)
                        mma8(acc[im][in], afr[im], bfr[in]);
            }
        }

        // epilogue: bias + store fp32
        #pragma unroll
        for (int im = 0; im < 4; ++im) {
            #pragma unroll
            for (int in = 0; in < 8; ++in) {
                int r  = wm + im * 16 + lr;
                int cN = wn + in * 8 + lc * 2;
                int gc = n2 * 256 + cN;
                float bb0 = __ldg(w2_b + e * DIM + gc);
                float bb1 = __ldg(w2_b + e * DIM + gc + 1);
                float2 v0 = make_float2(acc[im][in][0] + bb0, acc[im][in][1] + bb1);
                float2 v1 = make_float2(acc[im][in][2] + bb0, acc[im][in][3] + bb1);
                *(float2*)(out + ((size_t)(s0 + r) * BZ + b) * DIM + gc)     = v0;
                *(float2*)(out + ((size_t)(s0 + r + 8) * BZ + b) * DIM + gc) = v1;
            }
        }
    }
}

}  // namespace

extern "C" void kernel_launch(void* const* d_in, const int* in_sizes, int n_in,
                              void* d_out, int out_size) {
    const float* x        = (const float*)d_in[0];
    const int*   lang_ids = (const int*)  d_in[1];
    const float* w1_w     = (const float*)d_in[2];
    const float* w1_b     = (const float*)d_in[3];
    const float* w2_w     = (const float*)d_in[4];
    const float* w2_b     = (const float*)d_in[5];
    float*       out      = (float*)d_out;

    cudaFuncSetAttribute(switcher_kernel,
                         cudaFuncAttributeMaxDynamicSharedMemorySize, SMEM_BYTES);

    // prepass: fp32 -> tf32 weights (4 MB, ~2us)
    convert_weights<<<512, 256>>>(w1_w, w2_w);

    dim3 grid(SEQ / TILE_S, BZ);
    switcher_kernel<<<grid, 256, SMEM_BYTES>>>(x, lang_ids, w1_b, w2_b, out);
}

// round 13
// speedup vs baseline: 1.0026x; 1.0020x over previous
#include <cuda_runtime.h>
#include <cstdint>
#include <math.h>

// ---------------------------------------------------------------------------
// Switcher: per-batch-column 2-expert MLP, tf32 mma.sync, fp32 accum.
//   e(b) = lang_ids[b] >= 12
//   out[s,b,:] = W2_e @ gelu(W1_e @ x[s,b,:] + b1_e) + b2_e  (exact erf gelu)
//
// R5: cp.async double-buffered pipeline.
//  - prepass converts W1/W2 to tf32 (rna) into __device__ scratch
//  - unified 64-chunk ring: chunks 0..31 = stage1 (X tile + W1 tile),
//    chunks 32..63 = stage2 W2 tiles (4 N-groups x 8 K-chunks)
//  - one __syncthreads per chunk; cp.async for k+1 overlaps compute of k
//  - XOR-swizzled smem (conflict-free), biases via __ldg
// ---------------------------------------------------------------------------

namespace {

constexpr int SEQ    = 2048;
constexpr int BZ     = 64;
constexpr int DIM    = 1024;
constexpr int HID    = 256;
constexpr int TILE_S = 128;
constexpr int KC     = 32;

// smem word offsets
constexpr int SH_OFF = 0;                     // sH: [128][256] swizzled
constexpr int XB_OFF = 32768;                 // xbuf: 2 x [128][32] swizzled
constexpr int WB_OFF = XB_OFF + 2 * 4096;     // wbuf: 2 x [256][32] swizzled
constexpr int SMEM_WORDS = WB_OFF + 2 * 8192; // 57344 words
constexpr int SMEM_BYTES = SMEM_WORDS * 4;    // 229376 B (224 KB)

// pre-converted tf32 weights (values tf32-rounded, stored as u32)
__device__ uint32_t g_w1[2 * HID * DIM];
__device__ uint32_t g_w2[2 * DIM * HID];

__device__ __forceinline__ uint32_t f2tf(float x) {
    uint32_t u;
    asm("cvt.rna.tf32.f32 %0, %1;" : "=r"(u) : "f"(x));
    return u;
}

__device__ __forceinline__ void mma8(float d[4], const uint32_t a[4], const uint32_t b[2]) {
    asm volatile(
        "mma.sync.aligned.m16n8k8.row.col.f32.tf32.tf32.f32 "
        "{%0,%1,%2,%3}, {%4,%5,%6,%7}, {%8,%9}, {%0,%1,%2,%3};\n"
        : "+f"(d[0]), "+f"(d[1]), "+f"(d[2]), "+f"(d[3])
        : "r"(a[0]), "r"(a[1]), "r"(a[2]), "r"(a[3]),
          "r"(b[0]), "r"(b[1]));
}

__device__ __forceinline__ void cp16(uint32_t dst_smem, const void* src) {
    asm volatile("cp.async.cg.shared.global [%0], [%1], 16;\n"
                 :: "r"(dst_smem), "l"(src));
}

__device__ __forceinline__ float gelu_exact(float v) {
    return 0.5f * v * (1.0f + erff(v * 0.70710678118654752440f));
}

// ------------------------- prepass: fp32 -> tf32 ---------------------------
__global__ void __launch_bounds__(256)
convert_weights(const float* __restrict__ w1, const float* __restrict__ w2) {
    int i = (blockIdx.x * 256 + threadIdx.x) * 4;
    if (i < 2 * HID * DIM) {
        float4 a = *(const float4*)(w1 + i);
        *(uint4*)(g_w1 + i) = make_uint4(f2tf(a.x), f2tf(a.y), f2tf(a.z), f2tf(a.w));
        float4 c = *(const float4*)(w2 + i);
        *(uint4*)(g_w2 + i) = make_uint4(f2tf(c.x), f2tf(c.y), f2tf(c.z), f2tf(c.w));
    }
}

// ------------------------------ main kernel --------------------------------
__global__ void __launch_bounds__(256, 1)
switcher_kernel(const float* __restrict__ x,
                const int*   __restrict__ lang_ids,
                const float* __restrict__ w1_b,
                const float* __restrict__ w2_b,
                float*       __restrict__ out)
{
    extern __shared__ uint32_t smem[];
    uint32_t* sH = smem + SH_OFF;
    const uint32_t smem_u = (uint32_t)__cvta_generic_to_shared(smem);

    const int tid  = threadIdx.x;
    const int lane = tid & 31;
    const int warp = tid >> 5;
    const int lr   = lane >> 2;         // 0..7
    const int lc   = lane & 3;          // 0..3
    const int swz  = lr << 2;           // smem XOR swizzle for this thread's rows
    const int wm   = (warp >> 2) * 64;  // {0,64}
    const int wn   = (warp & 3) * 64;   // {0,64,128,192}

    const int s0 = blockIdx.x * TILE_S;
    const int b  = blockIdx.y;
    const int e  = (lang_ids[b] >= 12) ? 1 : 0;

    const uint32_t* w1 = g_w1 + (size_t)e * HID * DIM;
    const uint32_t* w2 = g_w2 + (size_t)e * DIM * HID;

    // issue cp.async for chunk c into buffer (c&1), then commit a group.
    auto issue = [&](int c) {
        const uint32_t dstX = smem_u + (XB_OFF + (c & 1) * 4096) * 4;
        const uint32_t dstW = smem_u + (WB_OFF + (c & 1) * 8192) * 4;
        if (c < 32) {
            const int kc = c * KC;
            #pragma unroll
            for (int it = 0; it < 4; ++it) {           // X tile: 128x32
                int unit = tid + it * 256;
                int r = unit >> 3, c4 = (unit & 7) << 2;
                cp16(dstX + (r * 32 + (c4 ^ ((r & 7) << 2))) * 4,
                     x + ((size_t)(s0 + r) * BZ + b) * DIM + kc + c4);
            }
            #pragma unroll
            for (int it = 0; it < 8; ++it) {           // W1 tile: 256x32
                int unit = tid + it * 256;
                int r = unit >> 3, c4 = (unit & 7) << 2;
                cp16(dstW + (r * 32 + (c4 ^ ((r & 7) << 2))) * 4,
                     w1 + (size_t)r * DIM + kc + c4);
            }
        } else {
            const int cc = c - 32;
            const int n2 = cc >> 3;
            const int kc = (cc & 7) * KC;
            const uint32_t* wsrc = w2 + (size_t)n2 * 256 * HID;
            #pragma unroll
            for (int it = 0; it < 8; ++it) {           // W2 tile: 256x32
                int unit = tid + it * 256;
                int r = unit >> 3, c4 = (unit & 7) << 2;
                cp16(dstW + (r * 32 + (c4 ^ ((r & 7) << 2))) * 4,
                     wsrc + (size_t)r * HID + kc + c4);
            }
        }
        asm volatile("cp.async.commit_group;\n");
    };

    float acc[4][8][4];
    #pragma unroll
    for (int im = 0; im < 4; ++im)
        #pragma unroll
        for (int in = 0; in < 8; ++in)
            #pragma unroll
            for (int q = 0; q < 4; ++q) acc[im][in][q] = 0.0f;

    issue(0);

    // ================= stage 1: H = gelu(X @ W1^T + b1) =================
    #pragma unroll 1
    for (int c = 0; c < 32; ++c) {
        const int p = c & 1;
        asm volatile("cp.async.wait_group 0;\n" ::: "memory");
        __syncthreads();
        issue(c + 1);

        const uint32_t* xt = smem + XB_OFF + p * 4096;
        const uint32_t* wt = smem + WB_OFF + p * 8192;

        #pragma unroll
        for (int ks = 0; ks < 4; ++ks) {
            const int kk   = ks * 8;
            const int col0 = (kk + lc) ^ swz;
            const int col1 = (kk + lc + 4) ^ swz;
            uint32_t afr[4][4], bfr[8][2];
            #pragma unroll
            for (int im = 0; im < 4; ++im) {
                int r = wm + im * 16 + lr;
                afr[im][0] = f2tf(__uint_as_float(xt[r * 32 + col0]));
                afr[im][1] = f2tf(__uint_as_float(xt[(r + 8) * 32 + col0]));
                afr[im][2] = f2tf(__uint_as_float(xt[r * 32 + col1]));
                afr[im][3] = f2tf(__uint_as_float(xt[(r + 8) * 32 + col1]));
            }
            #pragma unroll
            for (int in = 0; in < 8; ++in) {
                int n = wn + in * 8 + lr;
                bfr[in][0] = wt[n * 32 + col0];
                bfr[in][1] = wt[n * 32 + col1];
            }
            #pragma unroll
            for (int im = 0; im < 4; ++im)
                #pragma unroll
                for (int in = 0; in < 8; ++in)
                    mma8(acc[im][in], afr[im], bfr[in]);
        }
    }

    // epilogue: bias + exact gelu -> sH (tf32, swizzled). The first stage-2
    // chunk's __syncthreads orders these writes before any sH read.
    #pragma unroll
    for (int im = 0; im < 4; ++im) {
        #pragma unroll
        for (int in = 0; in < 8; ++in) {
            int r = wm + im * 16 + lr;
            int cN = wn + in * 8 + lc * 2;
            float bb0 = __ldg(w1_b + e * HID + cN);
            float bb1 = __ldg(w1_b + e * HID + cN + 1);
            int pc = cN ^ swz;
            uint32_t h00 = f2tf(gelu_exact(acc[im][in][0] + bb0));
            uint32_t h01 = f2tf(gelu_exact(acc[im][in][1] + bb1));
            uint32_t h10 = f2tf(gelu_exact(acc[im][in][2] + bb0));
            uint32_t h11 = f2tf(gelu_exact(acc[im][in][3] + bb1));
            *(uint2*)(sH + r * 256 + pc)       = make_uint2(h00, h01);
            *(uint2*)(sH + (r + 8) * 256 + pc) = make_uint2(h10, h11);
        }
    }

    // ============ stage 2: OUT = H @ W2^T + b2, 4 N-groups of 256 ============
    #pragma unroll 1
    for (int n2 = 0; n2 < 4; ++n2) {
        #pragma unroll
        for (int im = 0; im < 4; ++im)
            #pragma unroll
            for (int in = 0; in < 8; ++in)
                #pragma unroll
                for (int q = 0; q < 4; ++q) acc[im][in][q] = 0.0f;

        #pragma unroll 1
        for (int kci = 0; kci < 8; ++kci) {
            const int c = 32 + n2 * 8 + kci;
            const int p = c & 1;
            asm volatile("cp.async.wait_group 0;\n" ::: "memory");
            __syncthreads();
            if (c + 1 < 64) issue(c + 1);

            const uint32_t* wt = smem + WB_OFF + p * 8192;

            #pragma unroll
            for (int ks = 0; ks < 4; ++ks) {
                const int kkH = kci * KC + ks * 8;
                const int kkW = ks * 8;
                const int ch0 = (kkH + lc) ^ swz;
                const int ch1 = (kkH + lc + 4) ^ swz;
                const int cw0 = (kkW + lc) ^ swz;
                const int cw1 = (kkW + lc + 4) ^ swz;
                uint32_t afr[4][4], bfr[8][2];
                #pragma unroll
                for (int im = 0; im < 4; ++im) {
                    int r = wm + im * 16 + lr;
                    afr[im][0] = sH[r * 256 + ch0];
                    afr[im][1] = sH[(r + 8) * 256 + ch0];
                    afr[im][2] = sH[r * 256 + ch1];
                    afr[im][3] = sH[(r + 8) * 256 + ch1];
                }
                #pragma unroll
                for (int in = 0; in < 8; ++in) {
                    int n = wn + in * 8 + lr;
                    bfr[in][0] = wt[n * 32 + cw0];
                    bfr[in][1] = wt[n * 32 + cw1];
                }
                #pragma unroll
                for (int im = 0; im < 4; ++im)
                    #pragma unroll
                    for (int in = 0; in < 8; ++in)
                        mma8(acc[im][in], afr[im], bfr[in]);
            }
        }

        // epilogue: bias + store fp32
        #pragma unroll
        for (int im = 0; im < 4; ++im) {
            #pragma unroll
            for (int in = 0; in < 8; ++in) {
                int r  = wm + im * 16 + lr;
                int cN = wn + in * 8 + lc * 2;
                int gc = n2 * 256 + cN;
                float bb0 = __ldg(w2_b + e * DIM + gc);
                float bb1 = __ldg(w2_b + e * DIM + gc + 1);
                float2 v0 = make_float2(acc[im][in][0] + bb0, acc[im][in][1] + bb1);
                float2 v1 = make_float2(acc[im][in][2] + bb0, acc[im][in][3] + bb1);
                *(float2*)(out + ((size_t)(s0 + r) * BZ + b) * DIM + gc)     = v0;
                *(float2*)(out + ((size_t)(s0 + r + 8) * BZ + b) * DIM + gc) = v1;
            }
        }
    }
}

}  // namespace

extern "C" void kernel_launch(void* const* d_in, const int* in_sizes, int n_in,
                              void* d_out, int out_size) {
    const float* x        = (const float*)d_in[0];
    const int*   lang_ids = (const int*)  d_in[1];
    const float* w1_w     = (const float*)d_in[2];
    const float* w1_b     = (const float*)d_in[3];
    const float* w2_w     = (const float*)d_in[4];
    const float* w2_b     = (const float*)d_in[5];
    float*       out      = (float*)d_out;

    cudaFuncSetAttribute(switcher_kernel,
                         cudaFuncAttributeMaxDynamicSharedMemorySize, SMEM_BYTES);

    // prepass: fp32 -> tf32 weights (4 MB, ~2us)
    convert_weights<<<512, 256>>>(w1_w, w2_w);

    dim3 grid(SEQ / TILE_S, BZ);
    switcher_kernel<<<grid, 256, SMEM_BYTES>>>(x, lang_ids, w1_b, w2_b, out);
}

// round 14
// speedup vs baseline: 1.0026x; 1.0000x over previous
#include <cuda_runtime.h>
#include <cstdint>
#include <math.h>

// ---------------------------------------------------------------------------
// Switcher: per-batch-column 2-expert MLP, tf32 mma.sync, fp32 accum.
//   e(b) = lang_ids[b] >= 12
//   out[s,b,:] = W2_e @ gelu(W1_e @ x[s,b,:] + b1_e) + b2_e  (exact erf gelu)
//
// R5: cp.async double-buffered pipeline.
//  - prepass converts W1/W2 to tf32 (rna) into __device__ scratch
//  - unified 64-chunk ring: chunks 0..31 = stage1 (X tile + W1 tile),
//    chunks 32..63 = stage2 W2 tiles (4 N-groups x 8 K-chunks)
//  - one __syncthreads per chunk; cp.async for k+1 overlaps compute of k
//  - XOR-swizzled smem (conflict-free), biases via __ldg
// ---------------------------------------------------------------------------

namespace {

constexpr int SEQ    = 2048;
constexpr int BZ     = 64;
constexpr int DIM    = 1024;
constexpr int HID    = 256;
constexpr int TILE_S = 128;
constexpr int KC     = 32;

// smem word offsets
constexpr int SH_OFF = 0;                     // sH: [128][256] swizzled
constexpr int XB_OFF = 32768;                 // xbuf: 2 x [128][32] swizzled
constexpr int WB_OFF = XB_OFF + 2 * 4096;     // wbuf: 2 x [256][32] swizzled
constexpr int SMEM_WORDS = WB_OFF + 2 * 8192; // 57344 words
constexpr int SMEM_BYTES = SMEM_WORDS * 4;    // 229376 B (224 KB)

// pre-converted tf32 weights (values tf32-rounded, stored as u32)
__device__ uint32_t g_w1[2 * HID * DIM];
__device__ uint32_t g_w2[2 * DIM * HID];

__device__ __forceinline__ uint32_t f2tf(float x) {
    uint32_t u;
    asm("cvt.rna.tf32.f32 %0, %1;" : "=r"(u) : "f"(x));
    return u;
}

__device__ __forceinline__ void mma8(float d[4], const uint32_t a[4], const uint32_t b[2]) {
    asm volatile(
        "mma.sync.aligned.m16n8k8.row.col.f32.tf32.tf32.f32 "
        "{%0,%1,%2,%3}, {%4,%5,%6,%7}, {%8,%9}, {%0,%1,%2,%3};\n"
        : "+f"(d[0]), "+f"(d[1]), "+f"(d[2]), "+f"(d[3])
        : "r"(a[0]), "r"(a[1]), "r"(a[2]), "r"(a[3]),
          "r"(b[0]), "r"(b[1]));
}

__device__ __forceinline__ void cp16(uint32_t dst_smem, const void* src) {
    asm volatile("cp.async.cg.shared.global [%0], [%1], 16;\n"
                 :: "r"(dst_smem), "l"(src));
}

__device__ __forceinline__ float gelu_exact(float v) {
    return 0.5f * v * (1.0f + erff(v * 0.70710678118654752440f));
}

// ------------------------- prepass: fp32 -> tf32 ---------------------------
__global__ void __launch_bounds__(256)
convert_weights(const float* __restrict__ w1, const float* __restrict__ w2) {
    int i = (blockIdx.x * 256 + threadIdx.x) * 4;
    if (i < 2 * HID * DIM) {
        float4 a = *(const float4*)(w1 + i);
        *(uint4*)(g_w1 + i) = make_uint4(f2tf(a.x), f2tf(a.y), f2tf(a.z), f2tf(a.w));
        float4 c = *(const float4*)(w2 + i);
        *(uint4*)(g_w2 + i) = make_uint4(f2tf(c.x), f2tf(c.y), f2tf(c.z), f2tf(c.w));
    }
}

// ------------------------------ main kernel --------------------------------
__global__ void __launch_bounds__(256, 1)
switcher_kernel(const float* __restrict__ x,
                const int*   __restrict__ lang_ids,
                const float* __restrict__ w1_b,
                const float* __restrict__ w2_b,
                float*       __restrict__ out)
{
    extern __shared__ uint32_t smem[];
    uint32_t* sH = smem + SH_OFF;
    const uint32_t smem_u = (uint32_t)__cvta_generic_to_shared(smem);

    const int tid  = threadIdx.x;
    const int lane = tid & 31;
    const int warp = tid >> 5;
    const int lr   = lane >> 2;         // 0..7
    const int lc   = lane & 3;          // 0..3
    const int swz  = lr << 2;           // smem XOR swizzle for this thread's rows
    const int wm   = (warp >> 2) * 64;  // {0,64}
    const int wn   = (warp & 3) * 64;   // {0,64,128,192}

    const int s0 = blockIdx.x * TILE_S;
    const int b  = blockIdx.y;
    const int e  = (lang_ids[b] >= 12) ? 1 : 0;

    const uint32_t* w1 = g_w1 + (size_t)e * HID * DIM;
    const uint32_t* w2 = g_w2 + (size_t)e * DIM * HID;

    // issue cp.async for chunk c into buffer (c&1), then commit a group.
    auto issue = [&](int c) {
        const uint32_t dstX = smem_u + (XB_OFF + (c & 1) * 4096) * 4;
        const uint32_t dstW = smem_u + (WB_OFF + (c & 1) * 8192) * 4;
        if (c < 32) {
            const int kc = c * KC;
            #pragma unroll
            for (int it = 0; it < 4; ++it) {           // X tile: 128x32
                int unit = tid + it * 256;
                int r = unit >> 3, c4 = (unit & 7) << 2;
                cp16(dstX + (r * 32 + (c4 ^ ((r & 7) << 2))) * 4,
                     x + ((size_t)(s0 + r) * BZ + b) * DIM + kc + c4);
            }
            #pragma unroll
            for (int it = 0; it < 8; ++it) {           // W1 tile: 256x32
                int unit = tid + it * 256;
                int r = unit >> 3, c4 = (unit & 7) << 2;
                cp16(dstW + (r * 32 + (c4 ^ ((r & 7) << 2))) * 4,
                     w1 + (size_t)r * DIM + kc + c4);
            }
        } else {
            const int cc = c - 32;
            const int n2 = cc >> 3;
            const int kc = (cc & 7) * KC;
            const uint32_t* wsrc = w2 + (size_t)n2 * 256 * HID;
            #pragma unroll
            for (int it = 0; it < 8; ++it) {           // W2 tile: 256x32
                int unit = tid + it * 256;
                int r = unit >> 3, c4 = (unit & 7) << 2;
                cp16(dstW + (r * 32 + (c4 ^ ((r & 7) << 2))) * 4,
                     wsrc + (size_t)r * HID + kc + c4);
            }
        }
        asm volatile("cp.async.commit_group;\n");
    };

    float acc[4][8][4];
    #pragma unroll
    for (int im = 0; im < 4; ++im)
        #pragma unroll
        for (int in = 0; in < 8; ++in)
            #pragma unroll
            for (int q = 0; q < 4; ++q) acc[im][in][q] = 0.0f;

    issue(0);

    // ================= stage 1: H = gelu(X @ W1^T + b1) =================
    #pragma unroll 1
    for (int c = 0; c < 32; ++c) {
        const int p = c & 1;
        asm volatile("cp.async.wait_group 0;\n" ::: "memory");
        __syncthreads();
        issue(c + 1);

        const uint32_t* xt = smem + XB_OFF + p * 4096;
        const uint32_t* wt = smem + WB_OFF + p * 8192;

        #pragma unroll
        for (int ks = 0; ks < 4; ++ks) {
            const int kk   = ks * 8;
            const int col0 = (kk + lc) ^ swz;
            const int col1 = (kk + lc + 4) ^ swz;
            uint32_t afr[4][4], bfr[8][2];
            #pragma unroll
            for (int im = 0; im < 4; ++im) {
                int r = wm + im * 16 + lr;
                afr[im][0] = f2tf(__uint_as_float(xt[r * 32 + col0]));
                afr[im][1] = f2tf(__uint_as_float(xt[(r + 8) * 32 + col0]));
                afr[im][2] = f2tf(__uint_as_float(xt[r * 32 + col1]));
                afr[im][3] = f2tf(__uint_as_float(xt[(r + 8) * 32 + col1]));
            }
            #pragma unroll
            for (int in = 0; in < 8; ++in) {
                int n = wn + in * 8 + lr;
                bfr[in][0] = wt[n * 32 + col0];
                bfr[in][1] = wt[n * 32 + col1];
            }
            #pragma unroll
            for (int im = 0; im < 4; ++im)
                #pragma unroll
                for (int in = 0; in < 8; ++in)
                    mma8(acc[im][in], afr[im], bfr[in]);
        }
    }

    // epilogue: bias + exact gelu -> sH (tf32, swizzled). The first stage-2
    // chunk's __syncthreads orders these writes before any sH read.
    #pragma unroll
    for (int im = 0; im < 4; ++im) {
        #pragma unroll
        for (int in = 0; in < 8; ++in) {
            int r = wm + im * 16 + lr;
            int cN = wn + in * 8 + lc * 2;
            float bb0 = __ldg(w1_b + e * HID + cN);
            float bb1 = __ldg(w1_b + e * HID + cN + 1);
            int pc = cN ^ swz;
            uint32_t h00 = f2tf(gelu_exact(acc[im][in][0] + bb0));
            uint32_t h01 = f2tf(gelu_exact(acc[im][in][1] + bb1));
            uint32_t h10 = f2tf(gelu_exact(acc[im][in][2] + bb0));
            uint32_t h11 = f2tf(gelu_exact(acc[im][in][3] + bb1));
            *(uint2*)(sH + r * 256 + pc)       = make_uint2(h00, h01);
            *(uint2*)(sH + (r + 8) * 256 + pc) = make_uint2(h10, h11);
        }
    }

    // ============ stage 2: OUT = H @ W2^T + b2, 4 N-groups of 256 ============
    #pragma unroll 1
    for (int n2 = 0; n2 < 4; ++n2) {
        #pragma unroll
        for (int im = 0; im < 4; ++im)
            #pragma unroll
            for (int in = 0; in < 8; ++in)
                #pragma unroll
                for (int q = 0; q < 4; ++q) acc[im][in][q] = 0.0f;

        #pragma unroll 1
        for (int kci = 0; kci < 8; ++kci) {
            const int c = 32 + n2 * 8 + kci;
            const int p = c & 1;
            asm volatile("cp.async.wait_group 0;\n" ::: "memory");
            __syncthreads();
            if (c + 1 < 64) issue(c + 1);

            const uint32_t* wt = smem + WB_OFF + p * 8192;

            #pragma unroll
            for (int ks = 0; ks < 4; ++ks) {
                const int kkH = kci * KC + ks * 8;
                const int kkW = ks * 8;
                const int ch0 = (kkH + lc) ^ swz;
                const int ch1 = (kkH + lc + 4) ^ swz;
                const int cw0 = (kkW + lc) ^ swz;
                const int cw1 = (kkW + lc + 4) ^ swz;
                uint32_t afr[4][4], bfr[8][2];
                #pragma unroll
                for (int im = 0; im < 4; ++im) {
                    int r = wm + im * 16 + lr;
                    afr[im][0] = sH[r * 256 + ch0];
                    afr[im][1] = sH[(r + 8) * 256 + ch0];
                    afr[im][2] = sH[r * 256 + ch1];
                    afr[im][3] = sH[(r + 8) * 256 + ch1];
                }
                #pragma unroll
                for (int in = 0; in < 8; ++in) {
                    int n = wn + in * 8 + lr;
                    bfr[in][0] = wt[n * 32 + cw0];
                    bfr[in][1] = wt[n * 32 + cw1];
                }
                #pragma unroll
                for (int im = 0; im < 4; ++im)
                    #pragma unroll
                    for (int in = 0; in < 8; ++in)
                        mma8(acc[im][in], afr[im], bfr[in]);
            }
        }

        // epilogue: bias + store fp32
        #pragma unroll
        for (int im = 0; im < 4; ++im) {
            #pragma unroll
            for (int in = 0; in < 8; ++in) {
                int r  = wm + im * 16 + lr;
                int cN = wn + in * 8 + lc * 2;
                int gc = n2 * 256 + cN;
                float bb0 = __ldg(w2_b + e * DIM + gc);
                float bb1 = __ldg(w2_b + e * DIM + gc + 1);
                float2 v0 = make_float2(acc[im][in][0] + bb0, acc[im][in][1] + bb1);
                float2 v1 = make_float2(acc[im][in][2] + bb0, acc[im][in][3] + bb1);
                *(float2*)(out + ((size_t)(s0 + r) * BZ + b) * DIM + gc)     = v0;
                *(float2*)(out + ((size_t)(s0 + r + 8) * BZ + b) * DIM + gc) = v1;
            }
        }
    }
}

}  // namespace

extern "C" void kernel_launch(void* const* d_in, const int* in_sizes, int n_in,
                              void* d_out, int out_size) {
    const float* x        = (const float*)d_in[0];
    const int*   lang_ids = (const int*)  d_in[1];
    const float* w1_w     = (const float*)d_in[2];
    const float* w1_b     = (const float*)d_in[3];
    const float* w2_w     = (const float*)d_in[4];
    const float* w2_b     = (const float*)d_in[5];
    float*       out      = (float*)d_out;

    cudaFuncSetAttribute(switcher_kernel,
                         cudaFuncAttributeMaxDynamicSharedMemorySize, SMEM_BYTES);

    // prepass: fp32 -> tf32 weights (4 MB, ~2us)
    convert_weights<<<512, 256>>>(w1_w, w2_w);

    dim3 grid(SEQ / TILE_S, BZ);
    switcher_kernel<<<grid, 256, SMEM_BYTES>>>(x, lang_ids, w1_b, w2_b, out);
}